// round 1
// baseline (speedup 1.0000x reference)
#include <cuda_runtime.h>
#include <math.h>

// ---------------------------------------------------------------------------
// DRMM matching score, GB300 (sm_103a)
//
// Reference math:
//   qn = q/( |q|+eps ), dn = d/( |d|+eps )
//   sim[b,q,d] = <qn, dn>
//   bin = clip( int((sim+1.000001)*0.5*10), 0, 10 )
//   hist[b,q,bin] += (qid>0 && did>0)
//   out_ffn[b] = sum log(hist+1e-5) * W1 + b1
//   score[b]  = out_ffn[b] * sum(softmax(gate)) == out_ffn[b]   (softmax sums to 1)
// The gating branch (Wg) is therefore dropped entirely.
// ---------------------------------------------------------------------------

#define BB   256
#define QQ   50
#define EE   50
#define DD   2000
#define NB   11
#define QB   (QQ * NB)      // 550
#define DTILE 512
#define NTHREADS 256

// scratch (no cudaMalloc allowed)
__device__ float g_qn[BB * QQ * EE];     // normalized query embeddings
__device__ float g_hist[BB * QB];        // global histogram (float counts)

// ---------------------------------------------------------------------------
// Kernel A: normalize q rows, zero histogram scratch
// one thread per (b,q) row; also zeroes its 11 hist entries
// ---------------------------------------------------------------------------
__global__ void prep_kernel(const float* __restrict__ qemb)
{
    int i = blockIdx.x * blockDim.x + threadIdx.x;   // row over B*Q
    if (i >= BB * QQ) return;

    const float* src = qemb + (size_t)i * EE;
    float v[EE];
    float ss = 0.f;
#pragma unroll
    for (int e = 0; e < EE; e++) { v[e] = src[e]; ss += v[e] * v[e]; }
    float r = 1.0f / (sqrtf(ss) + 1e-8f);
    float* dst = g_qn + (size_t)i * EE;
#pragma unroll
    for (int e = 0; e < EE; e++) dst[e] = v[e] * r;

#pragma unroll
    for (int k = 0; k < NB; k++) g_hist[i * NB + k] = 0.f;   // i*NB == b*QB + q*NB
}

// ---------------------------------------------------------------------------
// Kernel B: similarity + histogram
// grid (D/DTILE, B). Each thread owns 2 d-rows held in registers; qn[b] tile
// lives in smem (float2, broadcast reads). Per-block int histogram in smem,
// flushed with one float atomicAdd per entry.
// ---------------------------------------------------------------------------
__global__ void __launch_bounds__(NTHREADS, 1)
simhist_kernel(const float* __restrict__ demb,
               const int*   __restrict__ qids,
               const int*   __restrict__ dids)
{
    __shared__ float2 qn2[QQ * 26];    // 50 rows, padded to 26 float2 (52 floats)
    __shared__ int    hist_s[QB];
    __shared__ int    qv_s[QQ];

    const int b  = blockIdx.y;
    const int d0 = blockIdx.x * DTILE;
    const int t  = threadIdx.x;

    // stage normalized q tile (row-padded for alignment)
    const float2* qsrc = (const float2*)(g_qn + (size_t)b * QQ * EE);
    for (int i = t; i < QQ * 25; i += NTHREADS)
        qn2[(i / 25) * 26 + (i % 25)] = qsrc[i];
    for (int i = t; i < QB; i += NTHREADS) hist_s[i] = 0;
    if (t < QQ) qv_s[t] = (qids[b * QQ + t] > 0) ? 1 : 0;
    __syncthreads();

    const int dA = d0 + t;
    const int dB = d0 + t + NTHREADS;
    const bool okA = (dA < DD);
    const bool okB = (dB < DD);

    // load both d-rows into registers (each 32B sector fully consumed by the
    // owning thread across consecutive float2 reads -> no DRAM over-fetch)
    float a0[EE], a1[EE];
    float ssA = 0.f, ssB = 0.f;
    {
        const float2* pA = (const float2*)(demb + ((size_t)b * DD + dA) * EE);
        const float2* pB = (const float2*)(demb + ((size_t)b * DD + dB) * EE);
#pragma unroll
        for (int c = 0; c < 25; c++) {
            float2 v = make_float2(0.f, 0.f);
            if (okA) v = pA[c];
            a0[2 * c] = v.x; a0[2 * c + 1] = v.y;
            ssA += v.x * v.x + v.y * v.y;
            float2 w = make_float2(0.f, 0.f);
            if (okB) w = pB[c];
            a1[2 * c] = w.x; a1[2 * c + 1] = w.y;
            ssB += w.x * w.x + w.y * w.y;
        }
    }
    const float rA = 1.0f / (sqrtf(ssA) + 1e-8f);
    const float rB = 1.0f / (sqrtf(ssB) + 1e-8f);
    const bool addA = okA && (dids[b * DD + dA] > 0);
    const bool addB = okB && (dids[b * DD + dB] > 0);

    for (int q = 0; q < QQ; q++) {
        float s00 = 0.f, s01 = 0.f, s10 = 0.f, s11 = 0.f;
        const float2* w = &qn2[q * 26];
#pragma unroll
        for (int c = 0; c < 25; c++) {
            float2 wv = w[c];                 // broadcast LDS.64
            s00 = fmaf(a0[2 * c],     wv.x, s00);
            s01 = fmaf(a0[2 * c + 1], wv.y, s01);
            s10 = fmaf(a1[2 * c],     wv.x, s10);
            s11 = fmaf(a1[2 * c + 1], wv.y, s11);
        }
        if (qv_s[q]) {
            const int base = q * NB;
            if (addA) {
                float sim = (s00 + s01) * rA;
                int bin = (int)((sim + 1.000001f) * 0.5f * 10.0f);
                bin = min(max(bin, 0), NB - 1);
                atomicAdd(&hist_s[base + bin], 1);
            }
            if (addB) {
                float sim = (s10 + s11) * rB;
                int bin = (int)((sim + 1.000001f) * 0.5f * 10.0f);
                bin = min(max(bin, 0), NB - 1);
                atomicAdd(&hist_s[base + bin], 1);
            }
        }
    }

    __syncthreads();
    for (int i = t; i < QB; i += NTHREADS) {
        int c = hist_s[i];
        if (c) atomicAdd(&g_hist[(size_t)b * QB + i], (float)c);
    }
}

// ---------------------------------------------------------------------------
// Kernel C: out[b] = b1 + sum_i log(hist[b,i] + 1e-5) * W1[i]
// (gating softmax sums to 1 -> dropped)
// ---------------------------------------------------------------------------
__global__ void reduce_kernel(const float* __restrict__ W1,
                              const float* __restrict__ b1,
                              float* __restrict__ out)
{
    const int b = blockIdx.x;
    const int t = threadIdx.x;
    float p = 0.f;
    for (int i = t; i < QB; i += 256)
        p += logf(g_hist[(size_t)b * QB + i] + 1e-5f) * W1[i];

#pragma unroll
    for (int o = 16; o > 0; o >>= 1) p += __shfl_down_sync(0xffffffffu, p, o);

    __shared__ float red[8];
    if ((t & 31) == 0) red[t >> 5] = p;
    __syncthreads();
    if (t == 0) {
        float s = 0.f;
#pragma unroll
        for (int i = 0; i < 8; i++) s += red[i];
        out[b] = s + b1[0];
    }
}

// ---------------------------------------------------------------------------
extern "C" void kernel_launch(void* const* d_in, const int* in_sizes, int n_in,
                              void* d_out, int out_size)
{
    // defensive pointer selection by element count (falls back to declared order)
    const float* qemb = (const float*)d_in[0];   // 640000
    const float* demb = (const float*)d_in[1];   // 25600000
    const float* W1   = (const float*)d_in[2];   // 550
    const float* b1   = (const float*)d_in[3];   // 1
    const int*   qids = (const int*)d_in[5];     // 12800
    const int*   dids = (const int*)d_in[6];     // 512000
    for (int i = 0; i < n_in; i++) {
        switch (in_sizes[i]) {
            case BB * QQ * EE:  qemb = (const float*)d_in[i]; break;
            case BB * DD * EE:  demb = (const float*)d_in[i]; break;
            case QB:            W1   = (const float*)d_in[i]; break;
            case 1:             b1   = (const float*)d_in[i]; break;
            case BB * QQ:       qids = (const int*)d_in[i];   break;
            case BB * DD:       dids = (const int*)d_in[i];   break;
            default: break;     // Wg (2500) unused
        }
    }
    float* out = (float*)d_out;

    prep_kernel<<<(BB * QQ + 255) / 256, 256>>>(qemb);

    dim3 grid((DD + DTILE - 1) / DTILE, BB);   // (4, 256)
    simhist_kernel<<<grid, NTHREADS>>>(demb, qids, dids);

    reduce_kernel<<<BB, 256>>>(W1, b1, out);
}

// round 2
// speedup vs baseline: 1.0120x; 1.0120x over previous
#include <cuda_runtime.h>
#include <math.h>

// ---------------------------------------------------------------------------
// DRMM matching score, GB300 (sm_103a) — round 2
//   * packed fp32 FMA (fma.rn.f32x2) for the 1.28G-FMA cosine-sim GEMM
//   * q-normalization fused into the main kernel (prep_kernel removed)
//   * per-block private histogram slices (no global atomics, no zeroing pass)
//   * warp-aggregated shared-mem histogram atomics (__match_any_sync)
//   * gating branch dropped: softmax over batch sums to 1 exactly
// ---------------------------------------------------------------------------

#define BB   256
#define QQ   50
#define EE   50
#define DD   2000
#define NB   11
#define QB   (QQ * NB)        // 550
#define NTHREADS 256
#define DPB  500              // d-rows per block (4 slices cover D=2000 exactly)
#define NSLICE 4
#define QROW 52               // padded floats per q row (26 x 8B)

// per-(slice,batch) histogram slices — plain stores, summed in reduce kernel
__device__ int g_part[NSLICE * BB * QB];

__device__ __forceinline__ unsigned long long pack2(float x, float y) {
    unsigned long long r;
    asm("mov.b64 %0, {%1, %2};" : "=l"(r) : "f"(x), "f"(y));
    return r;
}
__device__ __forceinline__ void ffma2(unsigned long long& d,
                                      unsigned long long a,
                                      unsigned long long b) {
    asm("fma.rn.f32x2 %0, %1, %2, %0;" : "+l"(d) : "l"(a), "l"(b));
}
__device__ __forceinline__ float2 unpack2(unsigned long long v) {
    float2 r;
    asm("mov.b64 {%0, %1}, %2;" : "=f"(r.x), "=f"(r.y) : "l"(v));
    return r;
}

// ---------------------------------------------------------------------------
// Main kernel: grid (NSLICE, BB). Each thread owns 2 d-rows in registers
// (packed as 25 x b64). q tile staged raw in smem; norms folded as scalars.
// ---------------------------------------------------------------------------
__global__ void __launch_bounds__(NTHREADS, 2)
simhist_kernel(const float* __restrict__ qemb,
               const float* __restrict__ demb,
               const int*   __restrict__ qids,
               const int*   __restrict__ dids)
{
    __shared__ float qs[QQ * QROW];      // raw q rows, 8B-aligned rows
    __shared__ float rq_s[QQ];
    __shared__ int   hist_s[QB];
    __shared__ int   qv_s[QQ];

    const int b     = blockIdx.y;
    const int slice = blockIdx.x;
    const int d0    = slice * DPB;
    const int t     = threadIdx.x;
    const int lane  = t & 31;

    // stage raw q tile + zero histogram
    const float* qsrc = qemb + (size_t)b * QQ * EE;
    for (int i = t; i < QQ * EE; i += NTHREADS)
        qs[(i / EE) * QROW + (i % EE)] = qsrc[i];
    for (int i = t; i < QB; i += NTHREADS) hist_s[i] = 0;
    __syncthreads();

    // per-row q norms (threads 0..49), validity flags
    if (t < QQ) {
        const float* r = &qs[t * QROW];
        float ss = 0.f;
#pragma unroll
        for (int e = 0; e < EE; e++) ss += r[e] * r[e];
        rq_s[t] = 1.0f / (sqrtf(ss) + 1e-8f);
        qv_s[t] = (qids[b * QQ + t] > 0) ? 1 : 0;
    }

    // load this thread's two d-rows into packed registers (overlaps with above)
    const int dA = d0 + t;                       // always < DPB -> valid
    const int dB = d0 + t + NTHREADS;
    const bool okB = (t < DPB - NTHREADS);       // t < 244
    unsigned long long a0[25], a1[25];
    float ssA = 0.f, ssB = 0.f;
    {
        const float2* pA = (const float2*)(demb + ((size_t)b * DD + dA) * EE);
        const float2* pB = (const float2*)(demb + ((size_t)b * DD + dB) * EE);
#pragma unroll
        for (int c = 0; c < 25; c++) {
            float2 v = pA[c];
            ssA += v.x * v.x + v.y * v.y;
            a0[c] = pack2(v.x, v.y);
            float2 w = okB ? pB[c] : make_float2(0.f, 0.f);
            ssB += w.x * w.x + w.y * w.y;
            a1[c] = pack2(w.x, w.y);
        }
    }
    const float rA = 1.0f / (sqrtf(ssA) + 1e-8f);
    const float rB = 1.0f / (sqrtf(ssB) + 1e-8f);
    const bool addA = (dids[b * DD + dA] > 0);
    const bool addB = okB && (dids[b * DD + dB] > 0);
    const unsigned vbA = __ballot_sync(0xffffffffu, addA);
    const unsigned vbB = __ballot_sync(0xffffffffu, addB);
    __syncthreads();

    for (int q = 0; q < QQ; q++) {
        const unsigned long long* w = (const unsigned long long*)&qs[q * QROW];
        unsigned long long s0 = 0ull, s1 = 0ull;
#pragma unroll
        for (int c = 0; c < 25; c++) {
            unsigned long long wv = w[c];        // broadcast LDS.64
            ffma2(s0, a0[c], wv);
            ffma2(s1, a1[c], wv);
        }
        if (!qv_s[q]) continue;                  // uniform across block
        const float rqv = rq_s[q];
        const int base = q * NB;

        float2 u0 = unpack2(s0);
        float simA = (u0.x + u0.y) * (rA * rqv);
        int binA = (int)((simA + 1.000001f) * 0.5f * 10.0f);
        binA = min(max(binA, 0), NB - 1);
        unsigned mA = __match_any_sync(0xffffffffu, binA) & vbA;
        if (addA && lane == (__ffs(mA) - 1))
            atomicAdd(&hist_s[base + binA], __popc(mA));

        float2 u1 = unpack2(s1);
        float simB = (u1.x + u1.y) * (rB * rqv);
        int binB = (int)((simB + 1.000001f) * 0.5f * 10.0f);
        binB = min(max(binB, 0), NB - 1);
        unsigned mB = __match_any_sync(0xffffffffu, binB) & vbB;
        if (addB && lane == (__ffs(mB) - 1))
            atomicAdd(&hist_s[base + binB], __popc(mB));
    }

    __syncthreads();
    // private slice write-out — no atomics
    int* dst = g_part + ((size_t)slice * BB + b) * QB;
    for (int i = t; i < QB; i += NTHREADS) dst[i] = hist_s[i];
}

// ---------------------------------------------------------------------------
// Reduce: out[b] = b1 + sum_i log(sum_slices hist + 1e-5) * W1[i]
// ---------------------------------------------------------------------------
__global__ void reduce_kernel(const float* __restrict__ W1,
                              const float* __restrict__ b1,
                              float* __restrict__ out)
{
    const int b = blockIdx.x;
    const int t = threadIdx.x;
    float p = 0.f;
    for (int i = t; i < QB; i += 256) {
        int h = g_part[((size_t)0 * BB + b) * QB + i]
              + g_part[((size_t)1 * BB + b) * QB + i]
              + g_part[((size_t)2 * BB + b) * QB + i]
              + g_part[((size_t)3 * BB + b) * QB + i];
        p += logf((float)h + 1e-5f) * W1[i];
    }
#pragma unroll
    for (int o = 16; o > 0; o >>= 1) p += __shfl_down_sync(0xffffffffu, p, o);

    __shared__ float red[8];
    if ((t & 31) == 0) red[t >> 5] = p;
    __syncthreads();
    if (t == 0) {
        float s = 0.f;
#pragma unroll
        for (int i = 0; i < 8; i++) s += red[i];
        out[b] = s + b1[0];
    }
}

// ---------------------------------------------------------------------------
extern "C" void kernel_launch(void* const* d_in, const int* in_sizes, int n_in,
                              void* d_out, int out_size)
{
    const float* qemb = (const float*)d_in[0];
    const float* demb = (const float*)d_in[1];
    const float* W1   = (const float*)d_in[2];
    const float* b1   = (const float*)d_in[3];
    const int*   qids = (const int*)d_in[5];
    const int*   dids = (const int*)d_in[6];
    for (int i = 0; i < n_in; i++) {
        switch (in_sizes[i]) {
            case BB * QQ * EE:  qemb = (const float*)d_in[i]; break;
            case BB * DD * EE:  demb = (const float*)d_in[i]; break;
            case QB:            W1   = (const float*)d_in[i]; break;
            case 1:             b1   = (const float*)d_in[i]; break;
            case BB * QQ:       qids = (const int*)d_in[i];   break;
            case BB * DD:       dids = (const int*)d_in[i];   break;
            default: break;     // Wg unused (softmax sums to 1)
        }
    }
    float* out = (float*)d_out;

    dim3 grid(NSLICE, BB);     // (4, 256)
    simhist_kernel<<<grid, NTHREADS>>>(qemb, demb, qids, dids);
    reduce_kernel<<<BB, 256>>>(W1, b1, out);
}